// round 3
// baseline (speedup 1.0000x reference)
#include <cuda_runtime.h>

// ---------------- device scratch (no allocations allowed) ----------------
#define NMAX 4096
__device__ float g_scores[NMAX];
__device__ float g_pm[NMAX * 3];   // xyz / RADIUS
__device__ float g_pc[NMAX * 3];   // xyz / (sqrt(2)*RADIUS)
__device__ float g_uv[NMAX * 6];   // tangent u,v
__device__ float g_h1[NMAX * 16];  // pre-groupnorm h
__device__ float g_h[NMAX * 16];   // groupnormed h
__device__ float g_nuv[NMAX * 9];  // [n, t1, t2]
__device__ float g_y[NMAX * 16];   // conv output
__device__ float g_y2[NMAX * 16];  // after no_w MLP
__device__ float g_yn[NMAX * 16];  // after gn_out

__device__ __forceinline__ float lk(float x) { return x >= 0.f ? x : 0.2f * x; }

__device__ __forceinline__ unsigned long long pk2(float a, float b) {
    unsigned long long r;
    asm("mov.b64 %0, {%1, %2};" : "=l"(r) : "f"(a), "f"(b));
    return r;
}
__device__ __forceinline__ unsigned long long ffma2(unsigned long long a,
                                                    unsigned long long b,
                                                    unsigned long long c) {
    unsigned long long d;
    asm("fma.rn.f32x2 %0, %1, %2, %3;" : "=l"(d) : "l"(a), "l"(b), "l"(c));
    return d;
}
__device__ __forceinline__ float2 unpk(unsigned long long v) {
    float2 f;
    asm("mov.b64 {%0, %1}, %2;" : "=f"(f.x), "=f"(f.y) : "l"(v));
    return f;
}
// packed relu via integer max on the ALU pipe (bits(relu(x)) == max((int)x, 0))
__device__ __forceinline__ unsigned long long relu2(unsigned long long v) {
    int lo, hi;
    asm("mov.b64 {%0, %1}, %2;" : "=r"(lo), "=r"(hi) : "l"(v));
    lo = lo > 0 ? lo : 0;
    hi = hi > 0 ? hi : 0;
    unsigned long long r;
    asm("mov.b64 %0, {%1, %2};" : "=l"(r) : "r"(lo), "r"(hi));
    return r;
}

// ---------------- Kernel A: per-point preprocessing ----------------
__global__ void kA(const float* __restrict__ xyz, const float* __restrict__ nrm,
                   const float* __restrict__ feats,
                   const float* __restrict__ osw1, const float* __restrict__ osb1,
                   const float* __restrict__ osw2, const float* __restrict__ osb2,
                   const float* __restrict__ niw1, const float* __restrict__ nib1,
                   const float* __restrict__ niw2, const float* __restrict__ nib2,
                   int N) {
    __shared__ float sOs1[256], sNi1[256], sNi2[256];
    __shared__ float sOsb1[16], sOsw2[16], sNib1[16], sNib2[16];
    int t = threadIdx.x;
    if (t < 256) { sOs1[t] = osw1[t]; sNi1[t] = niw1[t]; sNi2[t] = niw2[t]; }
    if (t < 16)  { sOsb1[t] = osb1[t]; sOsw2[t] = osw2[t]; sNib1[t] = nib1[t]; sNib2[t] = nib2[t]; }
    __syncthreads();
    int i = blockIdx.x * 256 + t;
    if (i >= N) return;

    float f[16];
#pragma unroll
    for (int k = 0; k < 16; k++) f[k] = feats[i * 16 + k];

    float sc = osb2[0];
#pragma unroll
    for (int u = 0; u < 16; u++) {
        float a = sOsb1[u];
#pragma unroll
        for (int k = 0; k < 16; k++) a = fmaf(f[k], sOs1[u * 16 + k], a);
        sc = fmaf(lk(a), sOsw2[u], sc);
    }
    g_scores[i] = sc;

    float px = xyz[i * 3 + 0], py = xyz[i * 3 + 1], pz = xyz[i * 3 + 2];
    const float invR = 1.f / 9.f;
    const float invRc = 1.f / (9.f * 1.4142135623730951f);
    g_pm[i * 3 + 0] = px * invR;  g_pm[i * 3 + 1] = py * invR;  g_pm[i * 3 + 2] = pz * invR;
    g_pc[i * 3 + 0] = px * invRc; g_pc[i * 3 + 1] = py * invRc; g_pc[i * 3 + 2] = pz * invRc;

    float nx = nrm[i * 3 + 0], ny = nrm[i * 3 + 1], nz = nrm[i * 3 + 2];
    float s = nz >= 0.f ? 1.f : -1.f;
    float a = -1.f / (s + nz);
    float b = nx * ny * a;
    g_uv[i * 6 + 0] = 1.f + s * nx * nx * a;
    g_uv[i * 6 + 1] = s * b;
    g_uv[i * 6 + 2] = -s * nx;
    g_uv[i * 6 + 3] = b;
    g_uv[i * 6 + 4] = s + ny * ny * a;
    g_uv[i * 6 + 5] = -ny;

    float h0[16];
#pragma unroll
    for (int u = 0; u < 16; u++) {
        float acc = sNib1[u];
#pragma unroll
        for (int k = 0; k < 16; k++) acc = fmaf(f[k], sNi1[u * 16 + k], acc);
        h0[u] = lk(acc);
    }
#pragma unroll
    for (int v = 0; v < 16; v++) {
        float acc = sNib2[v];
#pragma unroll
        for (int k = 0; k < 16; k++) acc = fmaf(h0[k], sNi2[v * 16 + k], acc);
        g_h1[i * 16 + v] = lk(acc);
    }
}

// ---------------- GroupNorm ----------------
__device__ void gn_body(const float* __restrict__ xin, const float* __restrict__ gamma,
                        const float* __restrict__ beta, float* __restrict__ xout, int N) {
    __shared__ float red[32][8];
    __shared__ float fin[8];
    __shared__ float smean[4], sinv[4];
    int t = threadIdx.x;
    float s0 = 0, s1 = 0, s2 = 0, s3 = 0, q0 = 0, q1 = 0, q2 = 0, q3 = 0;
    for (int n = t; n < N; n += blockDim.x) {
        const float4* r = reinterpret_cast<const float4*>(xin + n * 16);
        float4 v0 = r[0], v1 = r[1], v2 = r[2], v3 = r[3];
        s0 += v0.x + v0.y + v0.z + v0.w; q0 += v0.x * v0.x + v0.y * v0.y + v0.z * v0.z + v0.w * v0.w;
        s1 += v1.x + v1.y + v1.z + v1.w; q1 += v1.x * v1.x + v1.y * v1.y + v1.z * v1.z + v1.w * v1.w;
        s2 += v2.x + v2.y + v2.z + v2.w; q2 += v2.x * v2.x + v2.y * v2.y + v2.z * v2.z + v2.w * v2.w;
        s3 += v3.x + v3.y + v3.z + v3.w; q3 += v3.x * v3.x + v3.y * v3.y + v3.z * v3.z + v3.w * v3.w;
    }
#pragma unroll
    for (int off = 16; off > 0; off >>= 1) {
        s0 += __shfl_down_sync(0xffffffffu, s0, off);
        s1 += __shfl_down_sync(0xffffffffu, s1, off);
        s2 += __shfl_down_sync(0xffffffffu, s2, off);
        s3 += __shfl_down_sync(0xffffffffu, s3, off);
        q0 += __shfl_down_sync(0xffffffffu, q0, off);
        q1 += __shfl_down_sync(0xffffffffu, q1, off);
        q2 += __shfl_down_sync(0xffffffffu, q2, off);
        q3 += __shfl_down_sync(0xffffffffu, q3, off);
    }
    int lane = t & 31, w = t >> 5;
    if (lane == 0) {
        red[w][0] = s0; red[w][1] = s1; red[w][2] = s2; red[w][3] = s3;
        red[w][4] = q0; red[w][5] = q1; red[w][6] = q2; red[w][7] = q3;
    }
    __syncthreads();
    if (t < 8) {
        float a = 0;
        int nw = blockDim.x >> 5;
        for (int k = 0; k < nw; k++) a += red[k][t];
        fin[t] = a;
    }
    __syncthreads();
    if (t < 4) {
        float cnt = (float)(4 * N);
        float mn = fin[t] / cnt;
        float vv = fin[t + 4] / cnt - mn * mn;
        smean[t] = mn;
        sinv[t] = rsqrtf(vv + 1e-5f);
    }
    __syncthreads();
    for (int idx = t; idx < N * 16; idx += blockDim.x) {
        int c = idx & 15;
        int gg = c >> 2;
        xout[idx] = (xin[idx] - smean[gg]) * sinv[gg] * gamma[c] + beta[c];
    }
}
__global__ void kGN_in(const float* __restrict__ gamma, const float* __restrict__ beta, int N) {
    gn_body(g_h1, gamma, beta, g_h, N);
}
__global__ void kGN_out(const float* __restrict__ gamma, const float* __restrict__ beta, int N) {
    gn_body(g_y2, gamma, beta, g_yn, N);
}

// ---------------- Kernel C: load_mesh N^2 ----------------
__global__ void kMesh(const float* __restrict__ nrm, int N) {
    __shared__ float sred[8][16][2];
    int t = threadIdx.x;
    int il = t & 15, slice = t >> 4;
    int i = blockIdx.x * 16 + il;
    if (i >= N) return;

    float pix = g_pm[i * 3 + 0], piy = g_pm[i * 3 + 1], piz = g_pm[i * 3 + 2];
    float nix = nrm[i * 3 + 0], niy = nrm[i * 3 + 1], niz = nrm[i * 3 + 2];
    float ux = g_uv[i * 6 + 0], uy = g_uv[i * 6 + 1], uz = g_uv[i * 6 + 2];
    float vx = g_uv[i * 6 + 3], vy = g_uv[i * 6 + 4], vz = g_uv[i * 6 + 5];

    float ov0 = 0.f, ov1 = 0.f;
    int per = N >> 3;
    int j0 = slice * per;
    for (int j = j0; j < j0 + per; j++) {
        float dx = g_pm[j * 3 + 0] - pix;
        float dy = g_pm[j * 3 + 1] - piy;
        float dz = g_pm[j * 3 + 2] - piz;
        float d2 = dx * dx + dy * dy + dz * dz;
        float cs = nrm[j * 3 + 0] * nix + nrm[j * 3 + 1] * niy + nrm[j * 3 + 2] * niz;
        float tt = 2.f - cs;
        float wj = __expf(-d2 * tt * tt) * g_scores[j];
        ov0 = fmaf(wj, ux * dx + uy * dy + uz * dz, ov0);
        ov1 = fmaf(wj, vx * dx + vy * dy + vz * dz, ov1);
    }
    sred[slice][il][0] = ov0;
    sred[slice][il][1] = ov1;
    __syncthreads();
    if (slice == 0) {
#pragma unroll
        for (int k = 1; k < 8; k++) { ov0 += sred[k][il][0]; ov1 += sred[k][il][1]; }
        ov0 += 1e-5f; ov1 += 1e-5f;
        float nr = fmaxf(sqrtf(ov0 * ov0 + ov1 * ov1), 1e-12f);
        float ex = ov0 / nr, ey = ov1 / nr;
        g_nuv[i * 9 + 0] = nix; g_nuv[i * 9 + 1] = niy; g_nuv[i * 9 + 2] = niz;
        g_nuv[i * 9 + 3] = ex * ux + ey * vx;
        g_nuv[i * 9 + 4] = ex * uy + ey * vy;
        g_nuv[i * 9 + 5] = ex * uz + ey * vz;
        g_nuv[i * 9 + 6] = -ey * ux + ex * vx;
        g_nuv[i * 9 + 7] = -ey * uy + ex * vy;
        g_nuv[i * 9 + 8] = -ey * uz + ex * vz;
    }
}

// ---------------- Kernel D: main conv (h split 4-ways, wh pre-folded) ----------------
#define TI 4
#define TJ 64

__global__ void __launch_bounds__(256, 2)
kConv(const float* __restrict__ nrm, const float* __restrict__ cva1,
      const float* __restrict__ cvb1, const float* __restrict__ cva2,
      const float* __restrict__ cvb2, int N) {
    // sm_g[ii][c2][jj]: x = dup(g[2c2]), y = dup(g[2c2+1])
    __shared__ __align__(16) ulonglong2 sm_g[TI][4][TJ];
    __shared__ __align__(16) float sm_wh[TI][TJ][16];  // w * h
    __shared__ float sm_w[TI][TJ];
    __shared__ float sm_pi[TI][3];
    __shared__ float sm_nv[TI][9];
    __shared__ float sm_a1[24];
    __shared__ float sm_b1[8];
    __shared__ float sm_red[8][16];

    int t = threadIdx.x;
    int lane = t & 31, w = t >> 5;     // 8 warps
    int ii2 = w & 3;                   // phase-2 i index
    int o = lane & 15;
    int q = (lane >> 4) + 2 * (w >> 2);  // h-quarter 0..3 -> h's [4q, 4q+3]
    int ibase = blockIdx.x * TI;

    // per-thread packed weights: 2 chains, each an h-pair
    unsigned long long A2[2][8], B2[2];
#pragma unroll
    for (int c = 0; c < 2; c++) {
        int r = o * 16 + q * 4 + 2 * c;
#pragma unroll
        for (int k = 0; k < 8; k++) A2[c][k] = pk2(cva2[r * 8 + k], cva2[r * 8 + 8 + k]);
        B2[c] = pk2(cvb2[r], cvb2[r + 1]);
    }
    if (t < TI) {
        int i = ibase + t;
        sm_pi[t][0] = g_pc[i * 3 + 0];
        sm_pi[t][1] = g_pc[i * 3 + 1];
        sm_pi[t][2] = g_pc[i * 3 + 2];
#pragma unroll
        for (int k = 0; k < 9; k++) sm_nv[t][k] = g_nuv[i * 9 + k];
    }
    if (t >= 32 && t < 56) sm_a1[t - 32] = cva1[t - 32];
    if (t >= 64 && t < 72) sm_b1[t - 64] = cvb1[t - 64];
    __syncthreads();

    unsigned long long acc0 = 0ull, acc1 = 0ull;  // packed (+0,+0)
    for (int jt = 0; jt < N; jt += TJ) {
        // ---- phase 1a: all 256 threads, one (ii,jj) pair each ----
        {
            int ii1 = t >> 6, jj1 = t & 63;
            int j = jt + jj1;
            float pjx = g_pc[j * 3 + 0], pjy = g_pc[j * 3 + 1], pjz = g_pc[j * 3 + 2];
            float njx = nrm[j * 3 + 0], njy = nrm[j * 3 + 1], njz = nrm[j * 3 + 2];
            float dx = pjx - sm_pi[ii1][0];
            float dy = pjy - sm_pi[ii1][1];
            float dz = pjz - sm_pi[ii1][2];
            float d2 = dx * dx + dy * dy + dz * dz;
            float cs = njx * sm_nv[ii1][0] + njy * sm_nv[ii1][1] + njz * sm_nv[ii1][2];
            float tt = 2.f - cs;
            float wv = __expf(-d2 * tt * tt);
            float X0 = dx * sm_nv[ii1][0] + dy * sm_nv[ii1][1] + dz * sm_nv[ii1][2];
            float X1 = dx * sm_nv[ii1][3] + dy * sm_nv[ii1][4] + dz * sm_nv[ii1][5];
            float X2 = dx * sm_nv[ii1][6] + dy * sm_nv[ii1][7] + dz * sm_nv[ii1][8];
            sm_w[ii1][jj1] = wv;
            float gv[8];
#pragma unroll
            for (int c = 0; c < 8; c++) {
                float g = fmaf(X0, sm_a1[c * 3 + 0],
                          fmaf(X1, sm_a1[c * 3 + 1],
                          fmaf(X2, sm_a1[c * 3 + 2], sm_b1[c])));
                gv[c] = fmaxf(g, 0.f);
            }
#pragma unroll
            for (int c2 = 0; c2 < 4; c2++) {
                ulonglong2 v;
                v.x = pk2(gv[2 * c2], gv[2 * c2]);
                v.y = pk2(gv[2 * c2 + 1], gv[2 * c2 + 1]);
                sm_g[ii1][c2][jj1] = v;
            }
        }
        __syncthreads();
        // ---- phase 1b: wh = w * h, coalesced, conflict-free ----
#pragma unroll
        for (int r = 0; r < 4; r++) {
            int v = t + 256 * r;            // 0..1023 float4 slots
            int chunk = v & 3;
            int jj1 = (v >> 2) & 63;
            int ii1 = v >> 8;
            float wv = sm_w[ii1][jj1];
            float4 h4 = reinterpret_cast<const float4*>(g_h + (jt + jj1) * 16)[chunk];
            float4 r4;
            r4.x = wv * h4.x; r4.y = wv * h4.y; r4.z = wv * h4.z; r4.w = wv * h4.w;
            *reinterpret_cast<float4*>(&sm_wh[ii1][jj1][chunk * 4]) = r4;
        }
        __syncthreads();

        // ---- phase 2: two independent packed chains per thread ----
#pragma unroll 2
        for (int jj = 0; jj < TJ; jj++) {
            ulonglong2 gA = sm_g[ii2][0][jj];
            ulonglong2 gB = sm_g[ii2][1][jj];
            ulonglong2 gC = sm_g[ii2][2][jj];
            ulonglong2 gD = sm_g[ii2][3][jj];
            ulonglong2 whv = *reinterpret_cast<const ulonglong2*>(&sm_wh[ii2][jj][q * 4]);
            unsigned long long m0 = B2[0];
            unsigned long long m1 = B2[1];
            m0 = ffma2(A2[0][0], gA.x, m0);  m1 = ffma2(A2[1][0], gA.x, m1);
            m0 = ffma2(A2[0][1], gA.y, m0);  m1 = ffma2(A2[1][1], gA.y, m1);
            m0 = ffma2(A2[0][2], gB.x, m0);  m1 = ffma2(A2[1][2], gB.x, m1);
            m0 = ffma2(A2[0][3], gB.y, m0);  m1 = ffma2(A2[1][3], gB.y, m1);
            m0 = ffma2(A2[0][4], gC.x, m0);  m1 = ffma2(A2[1][4], gC.x, m1);
            m0 = ffma2(A2[0][5], gC.y, m0);  m1 = ffma2(A2[1][5], gC.y, m1);
            m0 = ffma2(A2[0][6], gD.x, m0);  m1 = ffma2(A2[1][6], gD.x, m1);
            m0 = ffma2(A2[0][7], gD.y, m0);  m1 = ffma2(A2[1][7], gD.y, m1);
            acc0 = ffma2(relu2(m0), whv.x, acc0);
            acc1 = ffma2(relu2(m1), whv.y, acc1);
        }
        __syncthreads();
    }
    float2 a0 = unpk(acc0), a1 = unpk(acc1);
    float v = (a0.x + a0.y) + (a1.x + a1.y);
    v += __shfl_xor_sync(0xffffffffu, v, 16);
    if (lane < 16) sm_red[w][o] = v;
    __syncthreads();
    if (t < 64) {
        int iiw = t >> 4, oo = t & 15;
        g_y[(ibase + iiw) * 16 + oo] = sm_red[iiw][oo] + sm_red[iiw + 4][oo];
    }
}

// ---------------- Kernel E1: y -> y2 (no_w MLP with leaky) ----------------
__global__ void kE1(const float* __restrict__ w1, const float* __restrict__ b1,
                    const float* __restrict__ w2, const float* __restrict__ b2, int N) {
    __shared__ float s1[256], s2[256], sb1[16], sb2[16];
    int t = threadIdx.x;
    if (t < 256) { s1[t] = w1[t]; s2[t] = w2[t]; }
    if (t < 16)  { sb1[t] = b1[t]; sb2[t] = b2[t]; }
    __syncthreads();
    int i = blockIdx.x * 256 + t;
    if (i >= N) return;
    float yv[16], t1[16];
#pragma unroll
    for (int k = 0; k < 16; k++) yv[k] = g_y[i * 16 + k];
#pragma unroll
    for (int u = 0; u < 16; u++) {
        float a = sb1[u];
#pragma unroll
        for (int k = 0; k < 16; k++) a = fmaf(yv[k], s1[u * 16 + k], a);
        t1[u] = lk(a);
    }
#pragma unroll
    for (int v = 0; v < 16; v++) {
        float a = sb2[v];
#pragma unroll
        for (int k = 0; k < 16; k++) a = fmaf(t1[k], s2[v * 16 + k], a);
        g_y2[i * 16 + v] = lk(a);
    }
}

// ---------------- Kernel E3: final heads + skip ----------------
__global__ void kE3(const float* __restrict__ feats,
                    const float* __restrict__ llw1, const float* __restrict__ llb1,
                    const float* __restrict__ llw2, const float* __restrict__ llb2,
                    const float* __restrict__ ltw, const float* __restrict__ ltb,
                    float* __restrict__ out, int N) {
    __shared__ float sW1[256], sW2[256], sWt[256], sB1[16], sB2[16], sBt[16];
    int t = threadIdx.x;
    if (t < 256) { sW1[t] = llw1[t]; sW2[t] = llw2[t]; sWt[t] = ltw[t]; }
    if (t < 16)  { sB1[t] = llb1[t]; sB2[t] = llb2[t]; sBt[t] = ltb[t]; }
    __syncthreads();
    int i = blockIdx.x * 256 + t;
    if (i >= N) return;
    float yn[16], f[16], t1[16];
#pragma unroll
    for (int k = 0; k < 16; k++) yn[k] = g_yn[i * 16 + k];
#pragma unroll
    for (int k = 0; k < 16; k++) f[k] = feats[i * 16 + k];
#pragma unroll
    for (int u = 0; u < 16; u++) {
        float a = sB1[u];
#pragma unroll
        for (int k = 0; k < 16; k++) a = fmaf(yn[k], sW1[u * 16 + k], a);
        t1[u] = fmaxf(a, 0.f);
    }
#pragma unroll
    for (int v = 0; v < 16; v++) {
        float xi = sB2[v];
#pragma unroll
        for (int k = 0; k < 16; k++) xi = fmaf(t1[k], sW2[v * 16 + k], xi);
        float xl = sBt[v];
#pragma unroll
        for (int k = 0; k < 16; k++) xl = fmaf(f[k], sWt[v * 16 + k], xl);
        out[i * 16 + v] = xl + xi;
    }
}

// ---------------- launch ----------------
extern "C" void kernel_launch(void* const* d_in, const int* in_sizes, int n_in,
                              void* d_out, int out_size) {
    const float* xyz    = (const float*)d_in[0];
    const float* nrm    = (const float*)d_in[1];
    const float* feats  = (const float*)d_in[2];
    const float* osw1   = (const float*)d_in[3];
    const float* osb1   = (const float*)d_in[4];
    const float* osw2   = (const float*)d_in[5];
    const float* osb2   = (const float*)d_in[6];
    const float* niw1   = (const float*)d_in[7];
    const float* nib1   = (const float*)d_in[8];
    const float* niw2   = (const float*)d_in[9];
    const float* nib2   = (const float*)d_in[10];
    const float* gnig   = (const float*)d_in[11];
    const float* gnib   = (const float*)d_in[12];
    const float* cva1   = (const float*)d_in[13];
    const float* cvb1   = (const float*)d_in[14];
    const float* cva2   = (const float*)d_in[15];
    const float* cvb2   = (const float*)d_in[16];
    const float* now1   = (const float*)d_in[17];
    const float* nob1   = (const float*)d_in[18];
    const float* now2   = (const float*)d_in[19];
    const float* nob2   = (const float*)d_in[20];
    const float* gnog   = (const float*)d_in[21];
    const float* gnob   = (const float*)d_in[22];
    const float* llw1   = (const float*)d_in[23];
    const float* llb1   = (const float*)d_in[24];
    const float* llw2   = (const float*)d_in[25];
    const float* llb2   = (const float*)d_in[26];
    const float* ltw    = (const float*)d_in[27];
    const float* ltb    = (const float*)d_in[28];
    float* out = (float*)d_out;

    int N = in_sizes[0] / 3;  // 4096

    kA<<<(N + 255) / 256, 256>>>(xyz, nrm, feats, osw1, osb1, osw2, osb2,
                                 niw1, nib1, niw2, nib2, N);
    kGN_in<<<1, 1024>>>(gnig, gnib, N);
    kMesh<<<N / 16, 128>>>(nrm, N);
    kConv<<<N / TI, 256>>>(nrm, cva1, cvb1, cva2, cvb2, N);
    kE1<<<(N + 255) / 256, 256>>>(now1, nob1, now2, nob2, N);
    kGN_out<<<1, 1024>>>(gnog, gnob, N);
    kE3<<<(N + 255) / 256, 256>>>(feats, llw1, llb1, llw2, llb2, ltw, ltb, out, N);
}